// round 14
// baseline (speedup 1.0000x reference)
#include <cuda_runtime.h>
#include <cuda_fp16.h>
#include <cstdint>

// CategorySpecificLinear on sm_103 family target (no tcgen05 in PTX target):
// out[n,m,h] = sum_k x[n,m,k] * W[cat[n],k,h] + b[cat[n],h]
// N=4096, M=16, K=256, H=256, 64 categories.
//
// R14: single fused kernel. Each of the 2*NSM persistent CTAs first runs a
// prep slice (W f32->fp16 transpose strips + per-category counting sort),
// crosses a resident-grid atomic barrier (2 CTAs/SM co-residency verified by
// host occupancy query; fallback = separate prep kernel), then runs the R13
// GEMM: cp.async-staged X, 1 barrier/K-chunk, direct-STG epilogue.
// fp16 mma.sync, fp32 acc (rel_err ~2.9e-4 measured).

#define K_DIM   256
#define H_DIM   256
#define M_ROWS  16
#define MAX_N   4096
#define NCAT    64
#define MAX_TILES (MAX_N / 8 + NCAT)     // 576
#define KC      64

__device__ int g_pad_sorted[MAX_TILES * 8];
__device__ int g_tile_cat[MAX_TILES];
__device__ int g_num_tiles;
__device__ unsigned g_bar = 0;           // monotonic; epoch = t / gridDim.x
__device__ __half g_Wt[NCAT * H_DIM * K_DIM];   // [cat][h][k] fp16

// ---------------- smem layout (bytes) ----------------
#define SM_A0      0                  // A buf: 128x64 fp16 = 16KB; x2
#define SM_ABUF_SZ 16384
#define SM_B       32768              // B buf: 128x64 fp16 = 16KB; x2
#define SM_BBUF_SZ 16384
#define SM_X       65536              // 128x64 f32 = 32KB
#define SM_TOTAL   98304              // 96KB -> 2 CTAs/SM
// prep phase overlays the same dynamic smem (needs 64*257*4 = 65792 B)

#define SWZ(row, c) (((uint32_t)(row)) * 128u + (((uint32_t)(c)) ^ ((((uint32_t)(row)) & 7u) << 4)))

__device__ __forceinline__ uint32_t smem_u32(const void* p) {
    uint32_t a;
    asm("{ .reg .u64 t; cvta.to.shared.u64 t, %1; cvt.u32.u64 %0, t; }" : "=r"(a) : "l"(p));
    return a;
}

#define CP_ASYNC16(dst, src) \
    asm volatile("cp.async.cg.shared.global [%0], [%1], 16;" :: "r"(dst), "l"(src) : "memory")
#define CP_COMMIT() asm volatile("cp.async.commit_group;" ::: "memory")
#define CP_WAIT0()  asm volatile("cp.async.wait_group 0;" ::: "memory")

#define LDSM_X4(r0, r1, r2, r3, addr) \
    asm volatile("ldmatrix.sync.aligned.m8n8.x4.shared.b16 {%0,%1,%2,%3}, [%4];" \
                 : "=r"(r0), "=r"(r1), "=r"(r2), "=r"(r3) : "r"(addr))

__device__ __forceinline__ void mma_f16(float* d, const uint32_t* a, uint32_t b0, uint32_t b1) {
    asm volatile(
        "mma.sync.aligned.m16n8k16.row.col.f32.f16.f16.f32 "
        "{%0,%1,%2,%3}, {%4,%5,%6,%7}, {%8,%9}, {%0,%1,%2,%3};"
        : "+f"(d[0]), "+f"(d[1]), "+f"(d[2]), "+f"(d[3])
        : "r"(a[0]), "r"(a[1]), "r"(a[2]), "r"(a[3]), "r"(b0), "r"(b1));
}

// ---------------- prep pieces (device functions, run in dynamic smem) ----------------
// wconv unit u (0..255): cat = u>>2, kstrip = u&3.
// Transposes W[cat][kstrip*64 .. +64][0..256] f32 -> g_Wt[cat][h][kstrip*64..] fp16.
__device__ void do_wconv_unit(const float* __restrict__ W, int unit, char* smem) {
    float* tile = (float*)smem;                // [64][257]
    const int cat = unit >> 2, kstrip = unit & 3;
    const int tid = threadIdx.x;
    const float* Wc = W + ((size_t)cat * K_DIM + kstrip * 64) * H_DIM;
    #pragma unroll
    for (int j = 0; j < 16; j++) {             // 64 rows x 64 float4
        int i = tid + j * 256;
        int row = i >> 6, f4 = i & 63;
        float4 v = *reinterpret_cast<const float4*>(Wc + (size_t)row * H_DIM + f4 * 4);
        float* dst = tile + row * 257 + f4 * 4;
        dst[0] = v.x; dst[1] = v.y; dst[2] = v.z; dst[3] = v.w;
    }
    __syncthreads();
    __half* Wo = g_Wt + (size_t)cat * H_DIM * K_DIM + kstrip * 64;
    #pragma unroll
    for (int j = 0; j < 8; j++) {              // 256 h-rows x 8 uint4
        int i = tid + j * 256;
        int h = i >> 3, ku = i & 7;
        __half tmp[8];
        #pragma unroll
        for (int c = 0; c < 8; c++)
            tmp[c] = __float2half_rn(tile[(ku * 8 + c) * 257 + h]);
        *reinterpret_cast<uint4*>(Wo + (size_t)h * K_DIM + ku * 8) =
            *reinterpret_cast<uint4*>(tmp);
    }
}

// per-category counting sort for category c (0..63)
__device__ void do_sort(const int* __restrict__ raw, int n, int c, char* smem) {
    __syncthreads();                           // protect smem reuse after wconv
    int* cnt = (int*)smem;                     // 64 ints
    int* misc = cnt + NCAT;                    // [0]=oddnz [1]=curs [2]=base
    const int t = threadIdx.x;
    if (t < NCAT) cnt[t] = 0;
    if (t == 0) { misc[0] = 0; misc[1] = 0; }
    __syncthreads();
    // int64 vs int32: int64 little-endian cats (<64) -> all odd words zero
    int local = 0;
    for (int i = t; i < n / 2; i += 256) local |= raw[2 * i + 1];
    if (local) atomicOr(&misc[0], 1);
    __syncthreads();
    const bool is64 = (misc[0] == 0);
    for (int i = t; i < n; i += 256) {
        int ci = (is64 ? raw[2 * i] : raw[i]) & (NCAT - 1);
        atomicAdd(&cnt[ci], 1);
    }
    __syncthreads();
    if (t == 0) {
        int toffT = 0;
        for (int c2 = 0; c2 < c; c2++) toffT += (cnt[c2] + 7) >> 3;
        const int ntc = (cnt[c] + 7) >> 3;
        misc[2] = toffT * 8;
        for (int tt = 0; tt < ntc; tt++) g_tile_cat[toffT + tt] = c;
        if (c == NCAT - 1) g_num_tiles = toffT + ntc;
    }
    __syncthreads();
    const int base = misc[2];
    const int ntc8 = ((cnt[c] + 7) >> 3) * 8;
    for (int i = t; i < ntc8; i += 256) g_pad_sorted[base + i] = -1;
    __syncthreads();
    for (int i = t; i < n; i += 256) {
        int ci = (is64 ? raw[2 * i] : raw[i]) & (NCAT - 1);
        if (ci == c) {
            int p = atomicAdd(&misc[1], 1);
            g_pad_sorted[base + p] = i;
        }
    }
}

// ---------------- standalone prep (fallback path only) ----------------
#define PREP_SMEM 66048
__global__ void __launch_bounds__(256)
prep_kernel(const float* __restrict__ W, const int* __restrict__ raw, int n) {
    extern __shared__ char smem[];
    if (blockIdx.x < 256) do_wconv_unit(W, blockIdx.x, smem);
    else                  do_sort(raw, n, blockIdx.x - 256, smem);
}

// ---------------- fused GEMM (persistent, 256 threads, 2 CTAs/SM) ----------------
// Work item w: sample-tile = w>>1, H-half = w&1 (columns [hh*128, hh*128+128)).
__global__ void __launch_bounds__(256, 2)
gemm_kernel(const float* __restrict__ x, const float* __restrict__ bias,
            float* __restrict__ out,
            const float* __restrict__ W, const int* __restrict__ raw, int n,
            int do_prep) {
    extern __shared__ char smem[];
    const uint32_t sbase = smem_u32(smem);
    const int tid = threadIdx.x;

    if (do_prep) {
        const int wblk = blockIdx.x;
        if (wblk < 256)  do_wconv_unit(W, wblk, smem);
        if (wblk >= 240) do_sort(raw, n, wblk - 240, smem);   // c = 0..63
        // resident-grid barrier (all gridDim.x CTAs co-resident; monotonic epoch)
        if (tid == 0) {
            __threadfence();
            unsigned t = atomicAdd(&g_bar, 1u);
            unsigned target = (t / gridDim.x + 1u) * gridDim.x;
            while (*((volatile unsigned*)&g_bar) < target) { }
            __threadfence();
        }
        __syncthreads();
    }

    const int wid = tid >> 5, lid = tid & 31;
    const int wm = wid >> 1, wn = wid & 1;        // 4M x 2N warp grid (N=128)
    const int g = lid >> 2, tig = lid & 3;

    // lane-invariant ldmatrix address components
    const uint32_t s7 = (uint32_t)(lid & 7) << 4;
    const int tl = lid >> 3;
    const uint32_t arow = (uint32_t)(wm * 32 + (tl & 1) * 8 + (lid & 7));
    const uint32_t brow = (uint32_t)(wn * 64 + (tl & 1) * 8 + (lid & 7));
    const uint32_t colsel = (uint32_t)((tl >> 1) * 16);

    auto issueB = [&](const __half* Wth, int kc) {
        const uint32_t bb = sbase + SM_B + (kc & 1) * SM_BBUF_SZ;
        const int k0 = kc * KC;
        #pragma unroll
        for (int j = 0; j < 4; j++) {       // 128 rows x 8 x 16B = 1024 / 256
            int i = tid + j * 256;
            int row = i >> 3, u = i & 7;
            uint32_t off = SWZ(row, u * 16);
            const char* src = (const char*)(Wth + (size_t)row * K_DIM + k0) + u * 16;
            CP_ASYNC16(bb + off, src);
        }
    };
    auto issueX = [&](int stile, int kc) {
        const int k0 = kc * KC;
        #pragma unroll
        for (int j = 0; j < 8; j++) {       // 128 rows x 16 x 16B = 2048 / 256
            int i = tid + j * 256;
            int row = i >> 4, u = i & 15;
            int id = __ldg(&g_pad_sorted[stile * 8 + (row >> 4)]);
            if (id < 0) id = 0;
            const char* src = (const char*)(x + (size_t)id * (M_ROWS * K_DIM)
                                            + (row & 15) * K_DIM + k0) + u * 16;
            CP_ASYNC16(sbase + SM_X + row * 256 + u * 16, src);
        }
    };
    // Converts exactly the X chunks this thread issued (same i-set) ->
    // valid right after CP_WAIT0, no barrier needed before it.
    auto convertA = [&](int abuf) {
        const float* Xs = (const float*)(smem + SM_X);
        const uint32_t ab = sbase + SM_A0 + abuf * SM_ABUF_SZ;
        #pragma unroll
        for (int j = 0; j < 8; j++) {
            int i = tid + j * 256;
            int row = i >> 4, f4 = i & 15;
            float4 v = *reinterpret_cast<const float4*>(Xs + row * 64 + f4 * 4);
            __half2 h01 = __halves2half2(__float2half_rn(v.x), __float2half_rn(v.y));
            __half2 h23 = __halves2half2(__float2half_rn(v.z), __float2half_rn(v.w));
            uint32_t off = SWZ(row, f4 * 8);
            asm volatile("st.shared.v2.b32 [%0], {%1, %2};"
                         :: "r"(ab + off), "r"(*(uint32_t*)&h01), "r"(*(uint32_t*)&h23)
                         : "memory");
        }
    };

    const int nwork = (*((volatile int*)&g_num_tiles)) * 2;

    // prefetch first work item's chunk 0
    if ((int)blockIdx.x < nwork) {
        const int st0 = blockIdx.x >> 1, hh0 = blockIdx.x & 1;
        const int cat0 = __ldg(&g_tile_cat[st0]);
        issueB(g_Wt + ((size_t)cat0 * H_DIM + hh0 * 128) * K_DIM, 0);
        issueX(st0, 0);
        CP_COMMIT();
    }

    for (int w = blockIdx.x; w < nwork; w += gridDim.x) {
        const int stile = w >> 1, hh = w & 1;
        const int cat = __ldg(&g_tile_cat[stile]);
        const __half* Wth = g_Wt + ((size_t)cat * H_DIM + hh * 128) * K_DIM;

        float acc[2][8][4];
        #pragma unroll
        for (int ma = 0; ma < 2; ma++)
            #pragma unroll
            for (int na = 0; na < 8; na++)
                #pragma unroll
                for (int r = 0; r < 4; r++) acc[ma][na][r] = 0.f;

        auto compute = [&](int kc) {
            const uint32_t aB = sbase + SM_A0 + (kc & 1) * SM_ABUF_SZ;
            const uint32_t bB = sbase + SM_B + (kc & 1) * SM_BBUF_SZ;
            #pragma unroll
            for (int ks = 0; ks < 4; ks++) {
                const uint32_t col = ((uint32_t)(ks * 32) + colsel) ^ s7;
                uint32_t af[2][4], bf[4][4];
                #pragma unroll
                for (int ma = 0; ma < 2; ma++) {
                    uint32_t aoff = (arow + ma * 16) * 128u + col;
                    LDSM_X4(af[ma][0], af[ma][1], af[ma][2], af[ma][3], aB + aoff);
                }
                #pragma unroll
                for (int nap = 0; nap < 4; nap++) {
                    uint32_t boff = (brow + nap * 16) * 128u + col;
                    LDSM_X4(bf[nap][0], bf[nap][1], bf[nap][2], bf[nap][3], bB + boff);
                }
                #pragma unroll
                for (int nap = 0; nap < 4; nap++)
                    #pragma unroll
                    for (int ma = 0; ma < 2; ma++) {
                        mma_f16(acc[ma][nap * 2],     af[ma], bf[nap][0], bf[nap][2]);
                        mma_f16(acc[ma][nap * 2 + 1], af[ma], bf[nap][1], bf[nap][3]);
                    }
            }
        };

        // ---- tile prologue: chunk 0 was prefetched during prev epilogue ----
        CP_WAIT0();
        convertA(0);
        __syncthreads();              // A0 + B0 visible to all warps
        issueB(Wth, 1); issueX(stile, 1); CP_COMMIT();

        // ---- mainloop: 1 syncthreads per kc ----
        for (int kc = 0; kc < 4; kc++) {
            compute(kc);
            if (kc < 3) {
                CP_WAIT0();
                convertA((kc + 1) & 1);
                __syncthreads();
                if (kc < 2) { issueB(Wth, kc + 2); issueX(stile, kc + 2); CP_COMMIT(); }
            }
        }

        // ---- cross-tile prefetch: next work item's chunk 0 during epilogue ----
        {
            const int nx = w + gridDim.x;
            if (nx < nwork) {
                const int stn = nx >> 1, hhn = nx & 1;
                const int catn = __ldg(&g_tile_cat[stn]);
                issueB(g_Wt + ((size_t)catn * H_DIM + hhn * 128) * K_DIM, 0);
                issueX(stn, 0);
                CP_COMMIT();
            }
        }

        // ---- epilogue: direct STG from fragments, bias via __ldg ----
        const float* bc = bias + cat * H_DIM + hh * 128;
        #pragma unroll
        for (int ma = 0; ma < 2; ma++) {
            const int r0 = wm * 32 + ma * 16 + g;
            const int id = __ldg(&g_pad_sorted[stile * 8 + (r0 >> 4)]);
            if (id >= 0) {
                float* o0 = out + (size_t)id * (M_ROWS * H_DIM) + (r0 & 15) * H_DIM + hh * 128;
                float* o8 = o0 + 8 * H_DIM;
                #pragma unroll
                for (int na = 0; na < 8; na++) {
                    const int colc = wn * 64 + na * 8 + 2 * tig;
                    const float2 bv = __ldg(reinterpret_cast<const float2*>(bc + colc));
                    *reinterpret_cast<float2*>(o0 + colc) =
                        make_float2(acc[ma][na][0] + bv.x, acc[ma][na][1] + bv.y);
                    *reinterpret_cast<float2*>(o8 + colc) =
                        make_float2(acc[ma][na][2] + bv.x, acc[ma][na][3] + bv.y);
                }
            }
        }
        // no barrier: epilogue touches only regs/global; A0/B0 prefetch aliasing
        // is safe (A0/B0 last read before the kc=2 barrier inside the mainloop).
    }
}

// ---------------- launch ----------------
extern "C" void kernel_launch(void* const* d_in, const int* in_sizes, int n_in,
                              void* d_out, int out_size) {
    const float* x   = (const float*)d_in[0];
    const int*   cid = (const int*)d_in[1];
    const float* W   = (const float*)d_in[2];
    const float* b   = (const float*)d_in[3];
    float* out = (float*)d_out;

    const int N = in_sizes[0] / (M_ROWS * K_DIM);

    int nsm = 0;
    cudaDeviceGetAttribute(&nsm, cudaDevAttrMultiProcessorCount, 0);
    if (nsm <= 0) nsm = 152;

    cudaFuncSetAttribute(gemm_kernel, cudaFuncAttributeMaxDynamicSharedMemorySize, SM_TOTAL);

    int occ = 0;
    cudaOccupancyMaxActiveBlocksPerMultiprocessor(&occ, gemm_kernel, 256, SM_TOTAL);

    if (occ >= 2) {
        // fused path: all 2*nsm CTAs co-resident -> prep + grid barrier + gemm
        gemm_kernel<<<2 * nsm, 256, SM_TOTAL>>>(x, b, out, W, cid, N, 1);
    } else {
        // fallback: separate prep kernel, no in-kernel barrier
        cudaFuncSetAttribute(prep_kernel, cudaFuncAttributeMaxDynamicSharedMemorySize, PREP_SMEM);
        prep_kernel<<<320, 256, PREP_SMEM>>>(W, cid, N);
        gemm_kernel<<<2 * nsm, 256, SM_TOTAL>>>(x, b, out, W, cid, N, 0);
    }
}

// round 15
// speedup vs baseline: 1.1184x; 1.1184x over previous
#include <cuda_runtime.h>
#include <cuda_fp16.h>
#include <cstdint>

// CategorySpecificLinear on sm_103 family target (no tcgen05 in PTX target):
// out[n,m,h] = sum_k x[n,m,k] * W[cat[n],k,h] + b[cat[n],h]
// N=4096, M=16, K=256, H=256, 64 categories.
//
// R15: R13 gemm structure, but W kept in ORIGINAL [cat][k][h] layout as fp16
// (prep = pure elementwise convert, no transpose) and B fragments loaded with
// ldmatrix.sync.trans. Prep cost collapses to streaming 24MB.
// fp16 mma.sync, fp32 acc (rel_err ~2.9e-4 measured).

#define K_DIM   256
#define H_DIM   256
#define M_ROWS  16
#define MAX_N   4096
#define NCAT    64
#define MAX_TILES (MAX_N / 8 + NCAT)     // 576
#define KC      64
#define NSM     152

__device__ int g_pad_sorted[MAX_TILES * 8];
__device__ int g_tile_cat[MAX_TILES];
__device__ int g_num_tiles;
__device__ __half g_Wt[NCAT * K_DIM * H_DIM];   // [cat][k][h] fp16 (NO transpose)

// ---------------- smem layout (bytes) ----------------
#define SM_A0      0                  // A buf: 128 m-rows x 128B = 16KB; x2
#define SM_ABUF_SZ 16384
#define SM_B       32768              // B buf: 64 k-rows x 256B = 16KB; x2
#define SM_BBUF_SZ 16384
#define SM_X       65536              // 128x64 f32 = 32KB
#define SM_TOTAL   98304              // 96KB -> 2 CTAs/SM

// A swizzle (128B rows): SWZ(row, c) = row*128 + (c ^ ((row&7)<<4))
#define SWZ(row, c) (((uint32_t)(row)) * 128u + (((uint32_t)(c)) ^ ((((uint32_t)(row)) & 7u) << 4)))
// B swizzle (256B k-rows): same XOR pattern keeps 8-row ldmatrix reads conflict-free
#define SWZB(row, c) (((uint32_t)(row)) * 256u + (((uint32_t)(c)) ^ ((((uint32_t)(row)) & 7u) << 4)))

__device__ __forceinline__ uint32_t smem_u32(const void* p) {
    uint32_t a;
    asm("{ .reg .u64 t; cvta.to.shared.u64 t, %1; cvt.u32.u64 %0, t; }" : "=r"(a) : "l"(p));
    return a;
}

#define CP_ASYNC16(dst, src) \
    asm volatile("cp.async.cg.shared.global [%0], [%1], 16;" :: "r"(dst), "l"(src) : "memory")
#define CP_COMMIT() asm volatile("cp.async.commit_group;" ::: "memory")
#define CP_WAIT0()  asm volatile("cp.async.wait_group 0;" ::: "memory")

#define LDSM_X4(r0, r1, r2, r3, addr) \
    asm volatile("ldmatrix.sync.aligned.m8n8.x4.shared.b16 {%0,%1,%2,%3}, [%4];" \
                 : "=r"(r0), "=r"(r1), "=r"(r2), "=r"(r3) : "r"(addr))
#define LDSM_X4T(r0, r1, r2, r3, addr) \
    asm volatile("ldmatrix.sync.aligned.m8n8.x4.trans.shared.b16 {%0,%1,%2,%3}, [%4];" \
                 : "=r"(r0), "=r"(r1), "=r"(r2), "=r"(r3) : "r"(addr))

__device__ __forceinline__ void mma_f16(float* d, const uint32_t* a, uint32_t b0, uint32_t b1) {
    asm volatile(
        "mma.sync.aligned.m16n8k16.row.col.f32.f16.f16.f32 "
        "{%0,%1,%2,%3}, {%4,%5,%6,%7}, {%8,%9}, {%0,%1,%2,%3};"
        : "+f"(d[0]), "+f"(d[1]), "+f"(d[2]), "+f"(d[3])
        : "r"(a[0]), "r"(a[1]), "r"(a[2]), "r"(a[3]), "r"(b0), "r"(b1));
}

// ---------------- prep: elementwise W convert (1024 blocks) + per-cat sort (64) ----------------
__global__ void __launch_bounds__(256)
prep_kernel(const float* __restrict__ W, const int* __restrict__ raw, int n) {
    if (blockIdx.x < 1024) {
        // pure streaming convert: f32 -> fp16, layout unchanged
        const float4* W4 = reinterpret_cast<const float4*>(W);
        uint2* Wh2 = reinterpret_cast<uint2*>(g_Wt);
        const int base = blockIdx.x * 1024;        // float4 units
        #pragma unroll
        for (int j = 0; j < 4; j++) {
            int i = base + j * 256 + threadIdx.x;
            float4 v = W4[i];
            __half2 h01 = __halves2half2(__float2half_rn(v.x), __float2half_rn(v.y));
            __half2 h23 = __halves2half2(__float2half_rn(v.z), __float2half_rn(v.w));
            Wh2[i] = make_uint2(*(uint32_t*)&h01, *(uint32_t*)&h23);
        }
        return;
    }
    // ---- per-category sort block: c = blockIdx.x - 1024 ----
    const int c = blockIdx.x - 1024;
    __shared__ int cnt[NCAT];
    __shared__ int oddnz, curs, base_s;
    const int t = threadIdx.x;
    if (t < NCAT) cnt[t] = 0;
    if (t == 0) { oddnz = 0; curs = 0; }
    __syncthreads();
    // int64 vs int32: int64 little-endian cats (<64) -> all odd words zero
    int local = 0;
    for (int i = t; i < n / 2; i += 256) local |= raw[2 * i + 1];
    if (local) atomicOr(&oddnz, 1);
    __syncthreads();
    const bool is64 = (oddnz == 0);
    for (int i = t; i < n; i += 256) {
        int ci = (is64 ? raw[2 * i] : raw[i]) & (NCAT - 1);
        atomicAdd(&cnt[ci], 1);
    }
    __syncthreads();
    if (t == 0) {
        int toffT = 0;
        for (int c2 = 0; c2 < c; c2++) toffT += (cnt[c2] + 7) >> 3;
        const int ntc = (cnt[c] + 7) >> 3;
        base_s = toffT * 8;
        for (int tt = 0; tt < ntc; tt++) g_tile_cat[toffT + tt] = c;
        if (c == NCAT - 1) g_num_tiles = toffT + ntc;
    }
    __syncthreads();
    const int base = base_s;
    const int ntc8 = ((cnt[c] + 7) >> 3) * 8;
    for (int i = t; i < ntc8; i += 256) g_pad_sorted[base + i] = -1;
    __syncthreads();
    for (int i = t; i < n; i += 256) {
        int ci = (is64 ? raw[2 * i] : raw[i]) & (NCAT - 1);
        if (ci == c) {
            int p = atomicAdd(&curs, 1);
            g_pad_sorted[base + p] = i;
        }
    }
}

// ---------------- GEMM (persistent, 256 threads, 2 CTAs/SM) ----------------
// Work item w: sample-tile = w>>1, H-half = w&1 (columns [hh*128, hh*128+128)).
__global__ void __launch_bounds__(256, 2)
gemm_kernel(const float* __restrict__ x, const float* __restrict__ b,
            float* __restrict__ out) {
    extern __shared__ char smem[];
    const uint32_t sbase = smem_u32(smem);
    const int tid = threadIdx.x;
    const int wid = tid >> 5, lid = tid & 31;
    const int wm = wid >> 1, wn = wid & 1;        // 4M x 2N warp grid (N=128)
    const int g = lid >> 2, tig = lid & 3;

    // lane-invariant ldmatrix address components
    const uint32_t s7 = (uint32_t)(lid & 7) << 4;
    const int tl = lid >> 3;
    const uint32_t arow = (uint32_t)(wm * 32 + (tl & 1) * 8 + (lid & 7));
    // B (.trans): lanes 0-7 -> k0-7 of h0-7; 8-15 -> k8-15 of h0-7;
    //             16-23 -> k0-7 of h8-15; 24-31 -> k8-15 of h8-15
    const uint32_t bkrow = (uint32_t)((tl & 1) * 8 + (lid & 7));
    const uint32_t bhsel = (uint32_t)((tl >> 1) * 16);   // bytes within 16-h block
    const uint32_t colsel = (uint32_t)((tl >> 1) * 16);

    // B source: g_Wt[cat][k][h]; chunk = k rows [k0,k0+64), h cols [hh*128,+128)
    auto issueB = [&](const __half* Wc, int hh, int kc) {
        const uint32_t bb = sbase + SM_B + (kc & 1) * SM_BBUF_SZ;
        const int k0 = kc * KC;
        #pragma unroll
        for (int j = 0; j < 4; j++) {       // 64 k-rows x 16 x 16B = 1024 / 256
            int i = tid + j * 256;
            int row = i >> 4, u = i & 15;
            uint32_t off = SWZB(row, u * 16);
            const char* src = (const char*)(Wc + (size_t)(k0 + row) * H_DIM + hh * 128) + u * 16;
            CP_ASYNC16(bb + off, src);
        }
    };
    auto issueX = [&](int stile, int kc) {
        const int k0 = kc * KC;
        #pragma unroll
        for (int j = 0; j < 8; j++) {       // 128 rows x 16 x 16B = 2048 / 256
            int i = tid + j * 256;
            int row = i >> 4, u = i & 15;
            int id = __ldg(&g_pad_sorted[stile * 8 + (row >> 4)]);
            if (id < 0) id = 0;
            const char* src = (const char*)(x + (size_t)id * (M_ROWS * K_DIM)
                                            + (row & 15) * K_DIM + k0) + u * 16;
            CP_ASYNC16(sbase + SM_X + row * 256 + u * 16, src);
        }
    };
    // Converts exactly the X chunks this thread issued (same i-set) ->
    // valid right after CP_WAIT0, no barrier needed before it.
    auto convertA = [&](int abuf) {
        const float* Xs = (const float*)(smem + SM_X);
        const uint32_t ab = sbase + SM_A0 + abuf * SM_ABUF_SZ;
        #pragma unroll
        for (int j = 0; j < 8; j++) {
            int i = tid + j * 256;
            int row = i >> 4, f4 = i & 15;
            float4 v = *reinterpret_cast<const float4*>(Xs + row * 64 + f4 * 4);
            __half2 h01 = __halves2half2(__float2half_rn(v.x), __float2half_rn(v.y));
            __half2 h23 = __halves2half2(__float2half_rn(v.z), __float2half_rn(v.w));
            uint32_t off = SWZ(row, f4 * 8);
            asm volatile("st.shared.v2.b32 [%0], {%1, %2};"
                         :: "r"(ab + off), "r"(*(uint32_t*)&h01), "r"(*(uint32_t*)&h23)
                         : "memory");
        }
    };

    const int nwork = g_num_tiles * 2;

    // prefetch first work item's chunk 0
    if ((int)blockIdx.x < nwork) {
        const int st0 = blockIdx.x >> 1, hh0 = blockIdx.x & 1;
        const int cat0 = __ldg(&g_tile_cat[st0]);
        issueB(g_Wt + (size_t)cat0 * K_DIM * H_DIM, hh0, 0);
        issueX(st0, 0);
        CP_COMMIT();
    }

    for (int w = blockIdx.x; w < nwork; w += gridDim.x) {
        const int stile = w >> 1, hh = w & 1;
        const int cat = __ldg(&g_tile_cat[stile]);
        const __half* Wc = g_Wt + (size_t)cat * K_DIM * H_DIM;

        float acc[2][8][4];
        #pragma unroll
        for (int ma = 0; ma < 2; ma++)
            #pragma unroll
            for (int na = 0; na < 8; na++)
                #pragma unroll
                for (int r = 0; r < 4; r++) acc[ma][na][r] = 0.f;

        auto compute = [&](int kc) {
            const uint32_t aB = sbase + SM_A0 + (kc & 1) * SM_ABUF_SZ;
            const uint32_t bB = sbase + SM_B + (kc & 1) * SM_BBUF_SZ;
            #pragma unroll
            for (int ks = 0; ks < 4; ks++) {
                const uint32_t acol = ((uint32_t)(ks * 32) + colsel) ^ s7;
                uint32_t af[2][4], bf[4][4];
                #pragma unroll
                for (int ma = 0; ma < 2; ma++) {
                    uint32_t aoff = (arow + ma * 16) * 128u + acol;
                    LDSM_X4(af[ma][0], af[ma][1], af[ma][2], af[ma][3], aB + aoff);
                }
                #pragma unroll
                for (int nap = 0; nap < 4; nap++) {
                    // 16k x 16h region at k = ks*16, h = wn*64 + nap*16
                    uint32_t boff = (ks * 16 + bkrow) * 256u
                                  + (((uint32_t)(wn * 128 + nap * 32) + bhsel) ^ s7);
                    LDSM_X4T(bf[nap][0], bf[nap][1], bf[nap][2], bf[nap][3], bB + boff);
                }
                // blocks: bf0=k0-7/h0-7, bf1=k8-15/h0-7, bf2=k0-7/h8-15, bf3=k8-15/h8-15
                #pragma unroll
                for (int nap = 0; nap < 4; nap++)
                    #pragma unroll
                    for (int ma = 0; ma < 2; ma++) {
                        mma_f16(acc[ma][nap * 2],     af[ma], bf[nap][0], bf[nap][1]);
                        mma_f16(acc[ma][nap * 2 + 1], af[ma], bf[nap][2], bf[nap][3]);
                    }
            }
        };

        // ---- tile prologue: chunk 0 was prefetched during prev epilogue ----
        CP_WAIT0();
        convertA(0);
        __syncthreads();              // A0 + B0 visible to all warps
        issueB(Wc, hh, 1); issueX(stile, 1); CP_COMMIT();

        // ---- mainloop: 1 syncthreads per kc ----
        for (int kc = 0; kc < 4; kc++) {
            compute(kc);
            if (kc < 3) {
                CP_WAIT0();
                convertA((kc + 1) & 1);
                __syncthreads();
                if (kc < 2) { issueB(Wc, hh, kc + 2); issueX(stile, kc + 2); CP_COMMIT(); }
            }
        }

        // ---- cross-tile prefetch: next work item's chunk 0 during epilogue ----
        {
            const int nx = w + gridDim.x;
            if (nx < nwork) {
                const int stn = nx >> 1, hhn = nx & 1;
                const int catn = __ldg(&g_tile_cat[stn]);
                issueB(g_Wt + (size_t)catn * K_DIM * H_DIM, hhn, 0);
                issueX(stn, 0);
                CP_COMMIT();
            }
        }

        // ---- epilogue: direct STG from fragments, bias via __ldg ----
        const float* bc = b + cat * H_DIM + hh * 128;
        #pragma unroll
        for (int ma = 0; ma < 2; ma++) {
            const int r0 = wm * 32 + ma * 16 + g;
            const int id = __ldg(&g_pad_sorted[stile * 8 + (r0 >> 4)]);
            if (id >= 0) {
                float* o0 = out + (size_t)id * (M_ROWS * H_DIM) + (r0 & 15) * H_DIM + hh * 128;
                float* o8 = o0 + 8 * H_DIM;
                #pragma unroll
                for (int na = 0; na < 8; na++) {
                    const int colc = wn * 64 + na * 8 + 2 * tig;
                    const float2 bv = __ldg(reinterpret_cast<const float2*>(bc + colc));
                    *reinterpret_cast<float2*>(o0 + colc) =
                        make_float2(acc[ma][na][0] + bv.x, acc[ma][na][1] + bv.y);
                    *reinterpret_cast<float2*>(o8 + colc) =
                        make_float2(acc[ma][na][2] + bv.x, acc[ma][na][3] + bv.y);
                }
            }
        }
        // no barrier: epilogue touches only regs/global; A0/B0 prefetch aliasing
        // is safe (A0/B0 last read before the kc=2 barrier inside the mainloop).
    }
}

// ---------------- launch ----------------
extern "C" void kernel_launch(void* const* d_in, const int* in_sizes, int n_in,
                              void* d_out, int out_size) {
    const float* x   = (const float*)d_in[0];
    const int*   cid = (const int*)d_in[1];
    const float* W   = (const float*)d_in[2];
    const float* b   = (const float*)d_in[3];
    float* out = (float*)d_out;

    const int N = in_sizes[0] / (M_ROWS * K_DIM);

    cudaFuncSetAttribute(gemm_kernel, cudaFuncAttributeMaxDynamicSharedMemorySize, SM_TOTAL);

    prep_kernel<<<1088, 256>>>(W, cid, N);
    gemm_kernel<<<NSM * 2, 256, SM_TOTAL>>>(x, b, out);
}